// round 13
// baseline (speedup 1.0000x reference)
#include <cuda_runtime.h>
#include <cuda_bf16.h>
#include <cstdint>
#include <math.h>

// Problem dims
#define BB   128
#define TT   1024
#define II   256
#define HH   512
#define G4H  2048

// ---------------- Phase 2 (lstm mma.sync) config ----------------
#define P2_GRID    64
#define P2_THREADS 256
#define KC2  64
#define NCH2 8
#define NROW 32                            // gate rows per CTA (8 h-cols)
#define WROW 1040                          // W_hh row stride bytes
#define SM_W    0                          // [2 split][32 n][1040] = 66,560
#define AROW 144                           // A row stride bytes
#define ABUF (2 * 128 * AROW)              // 36,864
#define SM_A    66560                      // [3 buf][2 split][128 m][144] = 110,592
#define SM_XG   177152                     // [2][32 r][128 b] f32 = 32,768
#define DSTR 36                            // D stage stride (f32)
#define SM_DST  209920                     // [128 m][36] f32 = 18,432
#define SM_TOTAL2 228352

// ---------------- Phase 1 (xgate mma.sync) config ----------------
#define G1_THREADS 256
#define WROW1 528
#define SM1_W    0                         // [2 split][64 n][528] = 67,584
#define SM1_A    67584                     // [4 buf][2 split][128 m][144]
#define SM1_BIAS (SM1_A + 4 * ABUF)        // 215,040
#define SM_TOTAL1 (SM1_BIAS + 256)         // 215,296

typedef unsigned long long ull;

// Scratch
__device__ float g_xg[(size_t)TT * G4H * BB];     // [t][prow][b]
__device__ __nv_bfloat16 g_h_hi[2][BB * HH];      // [buf][b][k]
__device__ __nv_bfloat16 g_h_lo[2][BB * HH];
__device__ __nv_bfloat16 g_x_hi[(size_t)TT * BB * II];  // [t][b][i]
__device__ __nv_bfloat16 g_x_lo[(size_t)TT * BB * II];
__device__ __nv_bfloat16 g_wih_hi[G4H * II];      // [prow][i]
__device__ __nv_bfloat16 g_wih_lo[G4H * II];
__device__ unsigned g_bar_count;
__device__ unsigned g_bar_gen;

// ---------- cp.async ----------
__device__ __forceinline__ void cp_async16(void* dst_smem, const void* src) {
    unsigned d = (unsigned)__cvta_generic_to_shared(dst_smem);
    asm volatile("cp.async.cg.shared.global [%0], [%1], 16;" :: "r"(d), "l"(src));
}
__device__ __forceinline__ void cp_commit() { asm volatile("cp.async.commit_group;"); }
template<int N> __device__ __forceinline__ void cp_wait() {
    asm volatile("cp.async.wait_group %0;" :: "n"(N));
}
__device__ __forceinline__ float sigf(float x) { return 1.0f / (1.0f + expf(-x)); }

__device__ __forceinline__ int prow_to_n(int prow) {
    int c2 = prow >> 4, r = prow & 15;
    return (r & 3) * HH + c2 * 4 + (r >> 2);
}
__device__ __forceinline__ uint32_t smem_u32(const void* p) {
    uint32_t a;
    asm("{ .reg .u64 t; cvta.to.shared.u64 t, %1; cvt.u32.u64 %0, t; }"
        : "=r"(a) : "l"(p));
    return a;
}
// ---------- mma.sync / ldmatrix ----------
__device__ __forceinline__ void ldsm4(uint32_t* r, uint32_t a) {
    asm volatile("ldmatrix.sync.aligned.m8n8.x4.shared.b16 {%0,%1,%2,%3}, [%4];"
        : "=r"(r[0]), "=r"(r[1]), "=r"(r[2]), "=r"(r[3]) : "r"(a));
}
__device__ __forceinline__ void mma_bf16(float* d, const uint32_t* a, const uint32_t* b) {
    asm volatile(
        "mma.sync.aligned.m16n8k16.row.col.f32.bf16.bf16.f32 "
        "{%0,%1,%2,%3}, {%4,%5,%6,%7}, {%8,%9}, {%0,%1,%2,%3};"
        : "+f"(d[0]), "+f"(d[1]), "+f"(d[2]), "+f"(d[3])
        : "r"(a[0]), "r"(a[1]), "r"(a[2]), "r"(a[3]), "r"(b[0]), "r"(b[1]));
}

// ---------- grid-wide barrier (monotonic count) ----------
__device__ __forceinline__ void grid_barrier(unsigned target) {
    __syncthreads();
    __threadfence();
    if (threadIdx.x == 0) {
        unsigned a = atomicAdd(&g_bar_count, 1u) + 1u;
        if (a == (unsigned)P2_GRID * target) {
            __threadfence();
            atomicAdd(&g_bar_gen, 1u);
        } else {
            while (*(volatile unsigned*)&g_bar_gen < target) { }
        }
        __threadfence();
    }
    __syncthreads();
}

// ============================================================================
// Prep: split x / W_ih to bf16 hi/lo, reset barrier.
// ============================================================================
__global__ void __launch_bounds__(256, 1) prep_kernel(
    const float* __restrict__ x, const float* __restrict__ W_ih)
{
    const int bl = blockIdx.x;
    const int tid = threadIdx.x;
    if (bl == 0 && tid == 0) { g_bar_count = 0u; g_bar_gen = 0u; }

    #pragma unroll 4
    for (int it = 0; it < 16; it++) {
        int row = bl * 16 + it;
        int b = row >> 10, t = row & 1023;
        float v = x[(size_t)row * II + tid];
        __nv_bfloat16 hi = __float2bfloat16(v);
        __nv_bfloat16 lo = __float2bfloat16(v - __bfloat162float(hi));
        size_t o = ((size_t)t * BB + b) * II + tid;
        g_x_hi[o] = hi;
        g_x_lo[o] = lo;
    }
    if (bl < G4H) {
        int n = prow_to_n(bl);
        float v = W_ih[(size_t)n * II + tid];
        __nv_bfloat16 hi = __float2bfloat16(v);
        __nv_bfloat16 lo = __float2bfloat16(v - __bfloat162float(hi));
        g_wih_hi[bl * II + tid] = hi;
        g_wih_lo[bl * II + tid] = lo;
    }
}

// ============================================================================
// Phase 1 (R11): xg via 3xBF16 mma.sync. Grid (32, 1024). M=128 N=64 K=256.
// ============================================================================
__global__ void __launch_bounds__(G1_THREADS, 1) xgate_kernel(
    const float* __restrict__ b_ih, const float* __restrict__ b_hh)
{
    extern __shared__ char smem[];
    const uint32_t sb = smem_u32(smem);
    const int tid = threadIdx.x;
    const int w = tid >> 5, l = tid & 31;
    const int gy = blockIdx.x;
    const int t  = blockIdx.y;

    #pragma unroll
    for (int j = 0; j < 16; j++) {
        int e = tid + j * G1_THREADS;
        int split = e >> 11, r = (e >> 5) & 63, u = e & 31;
        const __nv_bfloat16* src =
            (split ? g_wih_lo : g_wih_hi) + (size_t)(gy * 64 + r) * II + u * 8;
        cp_async16(smem + SM1_W + split * (64 * WROW1) + r * WROW1 + u * 16, src);
    }
    cp_commit();

    auto load_A = [&](int ci) {
        char* base = smem + SM1_A + (ci & 3) * ABUF;
        #pragma unroll
        for (int j = 0; j < 8; j++) {
            int e = l + j * 32;
            int split = e >> 7, m16 = (e >> 3) & 15, u = e & 7;
            int m = 16 * w + m16;
            const __nv_bfloat16* src =
                (split ? g_x_lo : g_x_hi) +
                ((size_t)t * BB + m) * II + ci * KC2 + u * 8;
            cp_async16(base + split * (128 * AROW) + m * AROW + u * 16, src);
        }
    };
    load_A(0); cp_commit();
    load_A(1); cp_commit();

    if (tid < 64) {
        int n = prow_to_n(gy * 64 + tid);
        ((float*)(smem + SM1_BIAS))[tid] = b_ih[n] + b_hh[n];
    }

    const int lm = l & 15, kh = l >> 4;
    const int brow = (l & 7) + ((l >> 4) << 3);
    const int bhalf = (l >> 3) & 1;
    const uint32_t aoff = (uint32_t)((16 * w + lm) * AROW + kh * 16);
    const uint32_t boff = (uint32_t)(brow * WROW1 + bhalf * 16);

    float d[8][4];
    #pragma unroll
    for (int i = 0; i < 8; i++)
        #pragma unroll
        for (int q = 0; q < 4; q++) d[i][q] = 0.f;

    #pragma unroll 1
    for (int ci = 0; ci < 4; ci++) {
        if (ci < 2) { load_A(ci + 2); cp_commit(); }
        else        { cp_commit(); }
        cp_wait<2>();
        if (ci == 0) __syncthreads();
        else         __syncwarp();

        const uint32_t Ab = sb + SM1_A + (ci & 3) * ABUF + aoff;
        const uint32_t Bb = sb + SM1_W + boff + ci * 128;
        #pragma unroll
        for (int ks = 0; ks < 4; ks++) {
            uint32_t ah[4], al[4];
            ldsm4(ah, Ab + ks * 32);
            ldsm4(al, Ab + 128 * AROW + ks * 32);
            #pragma unroll
            for (int g = 0; g < 4; g++) {
                uint32_t bh[4], bl[4];
                ldsm4(bh, Bb + g * 16 * WROW1 + ks * 32);
                ldsm4(bl, Bb + 64 * WROW1 + g * 16 * WROW1 + ks * 32);
                mma_bf16(d[2 * g],     ah, bh);
                mma_bf16(d[2 * g + 1], ah, bh + 2);
                mma_bf16(d[2 * g],     al, bh);
                mma_bf16(d[2 * g + 1], al, bh + 2);
                mma_bf16(d[2 * g],     ah, bl);
                mma_bf16(d[2 * g + 1], ah, bl + 2);
            }
        }
    }
    __syncthreads();

    {
        float* Ds = (float*)(smem + SM1_A);
        int m0 = 16 * w + (l >> 2);
        int c0 = 2 * (l & 3);
        #pragma unroll
        for (int g = 0; g < 4; g++) {
            *(float2*)&Ds[m0 * 72 + 16 * g + c0]           = make_float2(d[2*g][0], d[2*g][1]);
            *(float2*)&Ds[(m0 + 8) * 72 + 16 * g + c0]     = make_float2(d[2*g][2], d[2*g][3]);
            *(float2*)&Ds[m0 * 72 + 16 * g + 8 + c0]       = make_float2(d[2*g+1][0], d[2*g+1][1]);
            *(float2*)&Ds[(m0 + 8) * 72 + 16 * g + 8 + c0] = make_float2(d[2*g+1][2], d[2*g+1][3]);
        }
    }
    __syncthreads();

    {
        const float* Ds = (const float*)(smem + SM1_A);
        const float* bias_s = (const float*)(smem + SM1_BIAS);
        float* dst = g_xg + ((size_t)t * G4H + gy * 64) * BB;
        #pragma unroll 4
        for (int it = 0; it < 32; it++) {
            int e = it * G1_THREADS + tid;
            int r = e >> 7, b = e & 127;
            dst[e] = Ds[b * 72 + r] + bias_s[r];
        }
    }
}

// ============================================================================
// Phase 2: persistent mma.sync recurrence. 64 CTAs x 256 thr (8 warps).
// Per CTA/step: D[128 b x 32 rows] (8 h-cols). 3-buffer A ring, per-warp
// loads + __syncwarp only. Halved chip L2 h-traffic vs 128 CTAs.
// ============================================================================
__global__ void __launch_bounds__(P2_THREADS, 1) lstm_kernel(
    const float* __restrict__ W_hh, float* __restrict__ out)
{
    extern __shared__ char smem[];
    const uint32_t sb = smem_u32(smem);
    const int tid = threadIdx.x;
    const int w = tid >> 5, l = tid & 31;
    const int cta = blockIdx.x;

    // W_hh -> bf16 hi/lo tiles [split][32 n][1040B], once
    for (int idx = tid; idx < NROW * HH; idx += P2_THREADS) {
        int r = idx >> 9;
        int k = idx & 511;
        int n = prow_to_n(cta * NROW + r);
        float v = W_hh[(size_t)n * HH + k];
        __nv_bfloat16 hi = __float2bfloat16(v);
        __nv_bfloat16 lo = __float2bfloat16(v - __bfloat162float(hi));
        *(__nv_bfloat16*)(smem + SM_W + r * WROW + k * 2)               = hi;
        *(__nv_bfloat16*)(smem + SM_W + NROW * WROW + r * WROW + k * 2) = lo;
    }
    // Zero h buf0 own slice (8 cols x 128 b, both splits)
    {
        int b = tid & 127, half = tid >> 7;
        size_t off = (size_t)b * HH + cta * 8 + half * 4;
        *(ull*)&g_h_hi[0][off] = 0ull;
        *(ull*)&g_h_lo[0][off] = 0ull;
    }
    // Prefetch xg(0): 32 rows x 128 b f32 = 16 KB
    {
        const char* src = (const char*)(g_xg + ((size_t)cta * NROW) * BB);
        #pragma unroll
        for (int j = 0; j < 4; j++) {
            int e = tid + j * P2_THREADS;
            cp_async16(smem + SM_XG + e * 16, src + e * 16);
        }
        cp_commit();
    }

    // per-warp A chunk loader: warp w's rows 16w..16w+15 (ring of 3)
    auto load_A = [&](int ci, int hb) {
        char* base = smem + SM_A + (ci % 3) * ABUF;
        #pragma unroll
        for (int j = 0; j < 8; j++) {
            int e = l + j * 32;
            int split = e >> 7, m16 = (e >> 3) & 15, u = e & 7;
            int m = 16 * w + m16;
            const __nv_bfloat16* src =
                (split ? g_h_lo[hb] : g_h_hi[hb]) + (size_t)m * HH + ci * KC2 + u * 8;
            cp_async16(base + split * (128 * AROW) + m * AROW + u * 16, src);
        }
    };

    const int lm = l & 15, kh = l >> 4;
    const int brow = (l & 7) + ((l >> 4) << 3);
    const int bhalf = (l >> 3) & 1;
    const uint32_t aoff = (uint32_t)((16 * w + lm) * AROW + kh * 16);
    const uint32_t boff = (uint32_t)(brow * WROW + bhalf * 16);

    float cs[4] = {0.f, 0.f, 0.f, 0.f};
    unsigned gen = 0;
    grid_barrier(++gen);

    for (int t = 0; t < TT; t++) {
        const int hb = t & 1;
        load_A(0, hb); cp_commit();
        load_A(1, hb); cp_commit();

        float d0[4] = {0,0,0,0}, d1[4] = {0,0,0,0};
        float d2[4] = {0,0,0,0}, d3[4] = {0,0,0,0};

        #pragma unroll 1
        for (int ci = 0; ci < NCH2; ci++) {
            if (ci < NCH2 - 2) {
                load_A(ci + 2, hb);
                cp_commit();
            } else if (ci == NCH2 - 2) {
                if (t + 1 < TT) {
                    const char* src =
                        (const char*)(g_xg + ((size_t)(t + 1) * G4H + cta * NROW) * BB);
                    char* dd = smem + SM_XG + ((t + 1) & 1) * 16384;
                    #pragma unroll
                    for (int j = 0; j < 4; j++) {
                        int e = tid + j * P2_THREADS;
                        cp_async16(dd + e * 16, src + e * 16);
                    }
                }
                cp_commit();
            } else {
                cp_commit();
            }
            cp_wait<2>();
            __syncwarp();

            const uint32_t Ab = sb + SM_A + (ci % 3) * ABUF + aoff;
            const uint32_t Bb = sb + SM_W + boff + ci * 128;
            #pragma unroll
            for (int ks = 0; ks < 4; ks++) {
                uint32_t ah[4], al[4], bhA[4], bhB[4], blA[4], blB[4];
                ldsm4(ah, Ab + ks * 32);
                ldsm4(al, Ab + 128 * AROW + ks * 32);
                ldsm4(bhA, Bb + ks * 32);
                ldsm4(bhB, Bb + 16 * WROW + ks * 32);
                ldsm4(blA, Bb + NROW * WROW + ks * 32);
                ldsm4(blB, Bb + NROW * WROW + 16 * WROW + ks * 32);
                mma_bf16(d0, ah, bhA); mma_bf16(d1, ah, bhA + 2);
                mma_bf16(d2, ah, bhB); mma_bf16(d3, ah, bhB + 2);
                mma_bf16(d0, al, bhA); mma_bf16(d1, al, bhA + 2);
                mma_bf16(d2, al, bhB); mma_bf16(d3, al, bhB + 2);
                mma_bf16(d0, ah, blA); mma_bf16(d1, ah, blA + 2);
                mma_bf16(d2, ah, blB); mma_bf16(d3, ah, blB + 2);
            }
        }

        {
            float* Ds = (float*)(smem + SM_DST);
            int m0 = 16 * w + (l >> 2);
            int c0 = 2 * (l & 3);
            *(float2*)&Ds[m0 * DSTR + c0]            = make_float2(d0[0], d0[1]);
            *(float2*)&Ds[(m0 + 8) * DSTR + c0]      = make_float2(d0[2], d0[3]);
            *(float2*)&Ds[m0 * DSTR + c0 + 8]        = make_float2(d1[0], d1[1]);
            *(float2*)&Ds[(m0 + 8) * DSTR + c0 + 8]  = make_float2(d1[2], d1[3]);
            *(float2*)&Ds[m0 * DSTR + c0 + 16]       = make_float2(d2[0], d2[1]);
            *(float2*)&Ds[(m0 + 8) * DSTR + c0 + 16] = make_float2(d2[2], d2[3]);
            *(float2*)&Ds[m0 * DSTR + c0 + 24]       = make_float2(d3[0], d3[1]);
            *(float2*)&Ds[(m0 + 8) * DSTR + c0 + 24] = make_float2(d3[2], d3[3]);
        }
        __syncthreads();

        {
            const float* Ds = (const float*)(smem + SM_DST);
            const float* xg = (const float*)(smem + SM_XG + (t & 1) * 16384);
            const int b = tid & 127, half = tid >> 7;
            float hv[4];
            #pragma unroll
            for (int j = 0; j < 4; j++) {
                int hc = half * 4 + j;
                int pl = (hc >> 2) * 16 + (hc & 3) * 4;
                float gi = Ds[b * DSTR + pl + 0] + xg[(pl + 0) * BB + b];
                float gf = Ds[b * DSTR + pl + 1] + xg[(pl + 1) * BB + b];
                float gg = Ds[b * DSTR + pl + 2] + xg[(pl + 2) * BB + b];
                float go = Ds[b * DSTR + pl + 3] + xg[(pl + 3) * BB + b];
                float ig = sigf(gi), fg = sigf(gf), g2 = tanhf(gg), og = sigf(go);
                cs[j] = fg * cs[j] + ig * g2;
                hv[j] = og * tanhf(cs[j]);
            }
            size_t off = (size_t)b * HH + cta * 8 + half * 4;
            if (t < TT - 1) {
                __nv_bfloat16 hbf[4], lbf[4];
                #pragma unroll
                for (int j = 0; j < 4; j++) {
                    hbf[j] = __float2bfloat16(hv[j]);
                    lbf[j] = __float2bfloat16(hv[j] - __bfloat162float(hbf[j]));
                }
                *(ull*)&g_h_hi[(t + 1) & 1][off] = *(ull*)hbf;
                *(ull*)&g_h_lo[(t + 1) & 1][off] = *(ull*)lbf;
            } else {
                *(float4*)(out + off) = make_float4(hv[0], hv[1], hv[2], hv[3]);
            }
        }
        if (t < TT - 1) grid_barrier(++gen);
    }
}

extern "C" void kernel_launch(void* const* d_in, const int* in_sizes, int n_in,
                              void* d_out, int out_size) {
    const float* x    = (const float*)d_in[0];
    const float* W_ih = (const float*)d_in[1];
    const float* W_hh = (const float*)d_in[2];
    const float* b_ih = (const float*)d_in[3];
    const float* b_hh = (const float*)d_in[4];
    float* out = (float*)d_out;

    cudaFuncSetAttribute(xgate_kernel,
                         cudaFuncAttributeMaxDynamicSharedMemorySize, SM_TOTAL1);
    cudaFuncSetAttribute(lstm_kernel,
                         cudaFuncAttributeMaxDynamicSharedMemorySize, SM_TOTAL2);

    prep_kernel<<<8192, 256>>>(x, W_ih);
    xgate_kernel<<<dim3(32, TT), G1_THREADS, SM_TOTAL1>>>(b_ih, b_hh);
    lstm_kernel<<<P2_GRID, P2_THREADS, SM_TOTAL2>>>(W_hh, out);
}

// round 14
// speedup vs baseline: 1.1947x; 1.1947x over previous
#include <cuda_runtime.h>
#include <cuda_bf16.h>
#include <cstdint>
#include <math.h>

// Problem dims
#define BB   128
#define TT   1024
#define II   256
#define HH   512
#define G4H  2048

// ---------------- Phase 2 (lstm mma.sync) config ----------------
#define P2_GRID    128
#define P2_THREADS 256
#define KC2  128                           // k per chunk
#define NCH2 4                             // chunks per step
#define NROW 16                            // gate rows per CTA (4 h-cols)
#define WROW 1040                          // W_hh row stride bytes
#define SM_W    0                          // [2 split][16 n][1040] = 33,280
#define AROW 272                           // A row stride bytes (128*2+16)
#define ABUF (2 * 128 * AROW)              // 69,632
#define SM_A    33280                      // [2 buf][2 split][128 m][272] = 139,264
#define SM_XG   172544                     // [2][16 r][128 b] f32 = 16,384
#define SM_DST  188928                     // [128 m][18] f32 = 9,216
#define SM_TOTAL2 198144

// ---------------- Phase 1 (xgate mma.sync) config ----------------
#define G1_THREADS 256
#define KC1  64
#define AROW1 144
#define ABUF1 (2 * 128 * AROW1)            // 36,864
#define WROW1 528
#define SM1_W    0                         // [2 split][64 n][528] = 67,584
#define SM1_A    67584                     // [4 buf][2 split][128 m][144]
#define SM1_BIAS (SM1_A + 4 * ABUF1)       // 215,040
#define SM_TOTAL1 (SM1_BIAS + 256)         // 215,296

typedef unsigned long long ull;

// Scratch
__device__ float g_xg[(size_t)TT * G4H * BB];     // [t][prow][b]
__device__ __nv_bfloat16 g_h_hi[2][BB * HH];      // [buf][b][k]
__device__ __nv_bfloat16 g_h_lo[2][BB * HH];
__device__ __nv_bfloat16 g_x_hi[(size_t)TT * BB * II];  // [t][b][i]
__device__ __nv_bfloat16 g_x_lo[(size_t)TT * BB * II];
__device__ __nv_bfloat16 g_wih_hi[G4H * II];      // [prow][i]
__device__ __nv_bfloat16 g_wih_lo[G4H * II];
__device__ unsigned g_flags[P2_GRID * 32];        // 1 flag per CTA, 128B apart

// ---------- cp.async ----------
__device__ __forceinline__ void cp_async16(void* dst_smem, const void* src) {
    unsigned d = (unsigned)__cvta_generic_to_shared(dst_smem);
    asm volatile("cp.async.cg.shared.global [%0], [%1], 16;" :: "r"(d), "l"(src));
}
__device__ __forceinline__ void cp_commit() { asm volatile("cp.async.commit_group;"); }
template<int N> __device__ __forceinline__ void cp_wait() {
    asm volatile("cp.async.wait_group %0;" :: "n"(N));
}
__device__ __forceinline__ float sigf(float x) { return 1.0f / (1.0f + expf(-x)); }

__device__ __forceinline__ int prow_to_n(int prow) {
    int c2 = prow >> 4, r = prow & 15;
    return (r & 3) * HH + c2 * 4 + (r >> 2);
}
__device__ __forceinline__ uint32_t smem_u32(const void* p) {
    uint32_t a;
    asm("{ .reg .u64 t; cvta.to.shared.u64 t, %1; cvt.u32.u64 %0, t; }"
        : "=r"(a) : "l"(p));
    return a;
}
// ---------- mma.sync / ldmatrix ----------
__device__ __forceinline__ void ldsm4(uint32_t* r, uint32_t a) {
    asm volatile("ldmatrix.sync.aligned.m8n8.x4.shared.b16 {%0,%1,%2,%3}, [%4];"
        : "=r"(r[0]), "=r"(r[1]), "=r"(r[2]), "=r"(r[3]) : "r"(a));
}
__device__ __forceinline__ void mma_bf16(float* d, const uint32_t* a, const uint32_t* b) {
    asm volatile(
        "mma.sync.aligned.m16n8k16.row.col.f32.bf16.bf16.f32 "
        "{%0,%1,%2,%3}, {%4,%5,%6,%7}, {%8,%9}, {%0,%1,%2,%3};"
        : "+f"(d[0]), "+f"(d[1]), "+f"(d[2]), "+f"(d[3])
        : "r"(a[0]), "r"(a[1]), "r"(a[2]), "r"(a[3]), "r"(b[0]), "r"(b[1]));
}

// ---------- grid barrier: distributed flags, no atomics ----------
__device__ __forceinline__ void grid_barrier(unsigned gen, int cta, int tid) {
    __syncthreads();
    __threadfence();                       // h stores visible before flag
    if (tid == 0)
        *(volatile unsigned*)&g_flags[cta * 32] = gen;
    if (tid < P2_GRID) {
        while (*(volatile unsigned*)&g_flags[tid * 32] < gen) { }
    }
    __threadfence();                       // acquire: order subsequent reads
    __syncthreads();
}

// ============================================================================
// Prep: split x / W_ih to bf16 hi/lo, reset barrier flags.
// ============================================================================
__global__ void __launch_bounds__(256, 1) prep_kernel(
    const float* __restrict__ x, const float* __restrict__ W_ih)
{
    const int bl = blockIdx.x;
    const int tid = threadIdx.x;
    if (bl == 0 && tid < P2_GRID) g_flags[tid * 32] = 0u;

    #pragma unroll 4
    for (int it = 0; it < 16; it++) {
        int row = bl * 16 + it;
        int b = row >> 10, t = row & 1023;
        float v = x[(size_t)row * II + tid];
        __nv_bfloat16 hi = __float2bfloat16(v);
        __nv_bfloat16 lo = __float2bfloat16(v - __bfloat162float(hi));
        size_t o = ((size_t)t * BB + b) * II + tid;
        g_x_hi[o] = hi;
        g_x_lo[o] = lo;
    }
    if (bl < G4H) {
        int n = prow_to_n(bl);
        float v = W_ih[(size_t)n * II + tid];
        __nv_bfloat16 hi = __float2bfloat16(v);
        __nv_bfloat16 lo = __float2bfloat16(v - __bfloat162float(hi));
        g_wih_hi[bl * II + tid] = hi;
        g_wih_lo[bl * II + tid] = lo;
    }
}

// ============================================================================
// Phase 1 (R11, unchanged): xg via 3xBF16 mma.sync. Grid (32, 1024).
// ============================================================================
__global__ void __launch_bounds__(G1_THREADS, 1) xgate_kernel(
    const float* __restrict__ b_ih, const float* __restrict__ b_hh)
{
    extern __shared__ char smem[];
    const uint32_t sb = smem_u32(smem);
    const int tid = threadIdx.x;
    const int w = tid >> 5, l = tid & 31;
    const int gy = blockIdx.x;
    const int t  = blockIdx.y;

    #pragma unroll
    for (int j = 0; j < 16; j++) {
        int e = tid + j * G1_THREADS;
        int split = e >> 11, r = (e >> 5) & 63, u = e & 31;
        const __nv_bfloat16* src =
            (split ? g_wih_lo : g_wih_hi) + (size_t)(gy * 64 + r) * II + u * 8;
        cp_async16(smem + SM1_W + split * (64 * WROW1) + r * WROW1 + u * 16, src);
    }
    cp_commit();

    auto load_A = [&](int ci) {
        char* base = smem + SM1_A + (ci & 3) * ABUF1;
        #pragma unroll
        for (int j = 0; j < 8; j++) {
            int e = l + j * 32;
            int split = e >> 7, m16 = (e >> 3) & 15, u = e & 7;
            int m = 16 * w + m16;
            const __nv_bfloat16* src =
                (split ? g_x_lo : g_x_hi) +
                ((size_t)t * BB + m) * II + ci * KC1 + u * 8;
            cp_async16(base + split * (128 * AROW1) + m * AROW1 + u * 16, src);
        }
    };
    load_A(0); cp_commit();
    load_A(1); cp_commit();

    if (tid < 64) {
        int n = prow_to_n(gy * 64 + tid);
        ((float*)(smem + SM1_BIAS))[tid] = b_ih[n] + b_hh[n];
    }

    const int lm = l & 15, kh = l >> 4;
    const int brow = (l & 7) + ((l >> 4) << 3);
    const int bhalf = (l >> 3) & 1;
    const uint32_t aoff = (uint32_t)((16 * w + lm) * AROW1 + kh * 16);
    const uint32_t boff = (uint32_t)(brow * WROW1 + bhalf * 16);

    float d[8][4];
    #pragma unroll
    for (int i = 0; i < 8; i++)
        #pragma unroll
        for (int q = 0; q < 4; q++) d[i][q] = 0.f;

    #pragma unroll 1
    for (int ci = 0; ci < 4; ci++) {
        if (ci < 2) { load_A(ci + 2); cp_commit(); }
        else        { cp_commit(); }
        cp_wait<2>();
        if (ci == 0) __syncthreads();
        else         __syncwarp();

        const uint32_t Ab = sb + SM1_A + (ci & 3) * ABUF1 + aoff;
        const uint32_t Bb = sb + SM1_W + boff + ci * 128;
        #pragma unroll
        for (int ks = 0; ks < 4; ks++) {
            uint32_t ah[4], al[4];
            ldsm4(ah, Ab + ks * 32);
            ldsm4(al, Ab + 128 * AROW1 + ks * 32);
            #pragma unroll
            for (int g = 0; g < 4; g++) {
                uint32_t bh[4], bl[4];
                ldsm4(bh, Bb + g * 16 * WROW1 + ks * 32);
                ldsm4(bl, Bb + 64 * WROW1 + g * 16 * WROW1 + ks * 32);
                mma_bf16(d[2 * g],     ah, bh);
                mma_bf16(d[2 * g + 1], ah, bh + 2);
                mma_bf16(d[2 * g],     al, bh);
                mma_bf16(d[2 * g + 1], al, bh + 2);
                mma_bf16(d[2 * g],     ah, bl);
                mma_bf16(d[2 * g + 1], ah, bl + 2);
            }
        }
    }
    __syncthreads();

    {
        float* Ds = (float*)(smem + SM1_A);
        int m0 = 16 * w + (l >> 2);
        int c0 = 2 * (l & 3);
        #pragma unroll
        for (int g = 0; g < 4; g++) {
            *(float2*)&Ds[m0 * 72 + 16 * g + c0]           = make_float2(d[2*g][0], d[2*g][1]);
            *(float2*)&Ds[(m0 + 8) * 72 + 16 * g + c0]     = make_float2(d[2*g][2], d[2*g][3]);
            *(float2*)&Ds[m0 * 72 + 16 * g + 8 + c0]       = make_float2(d[2*g+1][0], d[2*g+1][1]);
            *(float2*)&Ds[(m0 + 8) * 72 + 16 * g + 8 + c0] = make_float2(d[2*g+1][2], d[2*g+1][3]);
        }
    }
    __syncthreads();

    {
        const float* Ds = (const float*)(smem + SM1_A);
        const float* bias_s = (const float*)(smem + SM1_BIAS);
        float* dst = g_xg + ((size_t)t * G4H + gy * 64) * BB;
        #pragma unroll 4
        for (int it = 0; it < 32; it++) {
            int e = it * G1_THREADS + tid;
            int r = e >> 7, b = e & 127;
            dst[e] = Ds[b * 72 + r] + bias_s[r];
        }
    }
}

// ============================================================================
// Phase 2: persistent mma.sync recurrence. 128 CTAs x 256 thr.
// KC=128 (4 chunks), double-buffer ring, prefetch-after-compute, uniform
// cp_wait<1>. Flag barrier (no atomics).
// ============================================================================
__global__ void __launch_bounds__(P2_THREADS, 1) lstm_kernel(
    const float* __restrict__ W_hh, float* __restrict__ out)
{
    extern __shared__ char smem[];
    const uint32_t sb = smem_u32(smem);
    const int tid = threadIdx.x;
    const int w = tid >> 5, l = tid & 31;
    const int cta = blockIdx.x;

    // W_hh -> bf16 hi/lo tiles, once
    for (int idx = tid; idx < NROW * HH; idx += P2_THREADS) {
        int r = idx >> 9;
        int k = idx & 511;
        int n = (r & 3) * HH + cta * 4 + (r >> 2);
        float v = W_hh[(size_t)n * HH + k];
        __nv_bfloat16 hi = __float2bfloat16(v);
        __nv_bfloat16 lo = __float2bfloat16(v - __bfloat162float(hi));
        *(__nv_bfloat16*)(smem + SM_W + r * WROW + k * 2)               = hi;
        *(__nv_bfloat16*)(smem + SM_W + NROW * WROW + r * WROW + k * 2) = lo;
    }
    // Zero h buf0 own slice (4 cols x 128 b, both splits)
    {
        int b = tid & 127, hcp = tid >> 7;
        __nv_bfloat162 z; z.x = __float2bfloat16(0.f); z.y = z.x;
        *(__nv_bfloat162*)&g_h_hi[0][(size_t)b * HH + cta * 4 + 2 * hcp] = z;
        *(__nv_bfloat162*)&g_h_lo[0][(size_t)b * HH + cta * 4 + 2 * hcp] = z;
    }
    // Prefetch xg(0): 16 rows x 128 b f32 = 8 KB
    {
        const char* src = (const char*)(g_xg + ((size_t)cta * NROW) * BB);
        cp_async16(smem + SM_XG + tid * 16, src + tid * 16);
        cp_async16(smem + SM_XG + (tid + 256) * 16, src + (tid + 256) * 16);
        cp_commit();
    }

    // per-warp A chunk loader: warp w's rows 16w..16w+15 (128 k per chunk)
    auto load_A = [&](int ci, int hb) {
        char* base = smem + SM_A + (ci & 1) * ABUF;
        #pragma unroll
        for (int j = 0; j < 16; j++) {
            int e = l + j * 32;              // 0..511
            int split = e >> 8, r = e & 255;
            int m16 = r >> 4, u = r & 15;
            int m = 16 * w + m16;
            const __nv_bfloat16* src =
                (split ? g_h_lo[hb] : g_h_hi[hb]) + (size_t)m * HH + ci * KC2 + u * 8;
            cp_async16(base + split * (128 * AROW) + m * AROW + u * 16, src);
        }
    };

    const int lm = l & 15, kh = l >> 4;
    const int brow = (l & 7) + ((l >> 4) << 3);
    const int bhalf = (l >> 3) & 1;
    const uint32_t aoff = (uint32_t)((16 * w + lm) * AROW + kh * 16);
    const uint32_t boff = (uint32_t)(brow * WROW + bhalf * 16);

    float cs[2] = {0.f, 0.f};
    unsigned gen = 1;
    grid_barrier(gen, cta, tid);   // W tiles + h0 + xg ordering

    for (int t = 0; t < TT; t++) {
        const int hb = t & 1;
        load_A(0, hb); cp_commit();
        load_A(1, hb); cp_commit();

        float d0[4] = {0.f, 0.f, 0.f, 0.f};
        float d1[4] = {0.f, 0.f, 0.f, 0.f};

        #pragma unroll 1
        for (int ci = 0; ci < NCH2; ci++) {
            cp_wait<1>();       // chunk ci done (one newer group may pend)
            __syncwarp();

            const uint32_t Ab = sb + SM_A + (ci & 1) * ABUF + aoff;
            const uint32_t Bb = sb + SM_W + boff + ci * 256;
            #pragma unroll
            for (int ks = 0; ks < 8; ks++) {
                uint32_t ah[4], al[4], bh[4], bl[4];
                ldsm4(ah, Ab + ks * 32);
                ldsm4(al, Ab + 128 * AROW + ks * 32);
                ldsm4(bh, Bb + ks * 32);
                ldsm4(bl, Bb + NROW * WROW + ks * 32);
                mma_bf16(d0, ah, bh);
                mma_bf16(d1, ah, bh + 2);
                mma_bf16(d0, al, bh);
                mma_bf16(d1, al, bh + 2);
                mma_bf16(d0, ah, bl);
                mma_bf16(d1, ah, bl + 2);
            }

            // prefetch AFTER compute: buffer (ci&1) is free for chunk ci+2
            if (ci < NCH2 - 2) {
                load_A(ci + 2, hb);
                cp_commit();
            } else if (ci == NCH2 - 2) {
                if (t + 1 < TT) {
                    const char* src =
                        (const char*)(g_xg + ((size_t)(t + 1) * G4H + cta * NROW) * BB);
                    char* dd = smem + SM_XG + ((t + 1) & 1) * 8192;
                    cp_async16(dd + tid * 16, src + tid * 16);
                    cp_async16(dd + (tid + 256) * 16, src + (tid + 256) * 16);
                }
                cp_commit();    // (possibly empty) keeps wait counting uniform
            }
        }

        {
            float* Ds = (float*)(smem + SM_DST);
            int m0 = 16 * w + (l >> 2);
            int c0 = 2 * (l & 3);
            *(float2*)&Ds[m0 * 18 + c0]           = make_float2(d0[0], d0[1]);
            *(float2*)&Ds[(m0 + 8) * 18 + c0]     = make_float2(d0[2], d0[3]);
            *(float2*)&Ds[m0 * 18 + c0 + 8]       = make_float2(d1[0], d1[1]);
            *(float2*)&Ds[(m0 + 8) * 18 + c0 + 8] = make_float2(d1[2], d1[3]);
        }
        __syncthreads();

        {
            const float* Ds = (const float*)(smem + SM_DST);
            const float* xg = (const float*)(smem + SM_XG + (t & 1) * 8192);
            const int b = tid & 127, hcp = tid >> 7;
            float hv[2];
            #pragma unroll
            for (int j = 0; j < 2; j++) {
                int r0 = (2 * hcp + j) * 4;
                float gi = Ds[b * 18 + r0 + 0] + xg[(r0 + 0) * BB + b];
                float gf = Ds[b * 18 + r0 + 1] + xg[(r0 + 1) * BB + b];
                float gg = Ds[b * 18 + r0 + 2] + xg[(r0 + 2) * BB + b];
                float go = Ds[b * 18 + r0 + 3] + xg[(r0 + 3) * BB + b];
                float ig = sigf(gi), fg = sigf(gf), g2 = tanhf(gg), og = sigf(go);
                cs[j] = fg * cs[j] + ig * g2;
                hv[j] = og * tanhf(cs[j]);
            }
            if (t < TT - 1) {
                __nv_bfloat16 h0 = __float2bfloat16(hv[0]);
                __nv_bfloat16 h1 = __float2bfloat16(hv[1]);
                __nv_bfloat16 l0 = __float2bfloat16(hv[0] - __bfloat162float(h0));
                __nv_bfloat16 l1 = __float2bfloat16(hv[1] - __bfloat162float(h1));
                __nv_bfloat162 ph; ph.x = h0; ph.y = h1;
                __nv_bfloat162 pl; pl.x = l0; pl.y = l1;
                size_t off = (size_t)b * HH + cta * 4 + 2 * hcp;
                *(__nv_bfloat162*)&g_h_hi[(t + 1) & 1][off] = ph;
                *(__nv_bfloat162*)&g_h_lo[(t + 1) & 1][off] = pl;
            } else {
                *(float2*)(out + (size_t)b * HH + cta * 4 + 2 * hcp) =
                    make_float2(hv[0], hv[1]);
            }
        }
        if (t < TT - 1) grid_barrier(++gen, cta, tid);
    }
}

extern "C" void kernel_launch(void* const* d_in, const int* in_sizes, int n_in,
                              void* d_out, int out_size) {
    const float* x    = (const float*)d_in[0];
    const float* W_ih = (const float*)d_in[1];
    const float* W_hh = (const float*)d_in[2];
    const float* b_ih = (const float*)d_in[3];
    const float* b_hh = (const float*)d_in[4];
    float* out = (float*)d_out;

    cudaFuncSetAttribute(xgate_kernel,
                         cudaFuncAttributeMaxDynamicSharedMemorySize, SM_TOTAL1);
    cudaFuncSetAttribute(lstm_kernel,
                         cudaFuncAttributeMaxDynamicSharedMemorySize, SM_TOTAL2);

    prep_kernel<<<8192, 256>>>(x, W_ih);
    xgate_kernel<<<dim3(32, TT), G1_THREADS, SM_TOTAL1>>>(b_ih, b_hh);
    lstm_kernel<<<P2_GRID, P2_THREADS, SM_TOTAL2>>>(W_hh, out);
}